// round 16
// baseline (speedup 1.0000x reference)
#include <cuda_runtime.h>
#include <cuda_bf16.h>
#include <math.h>
#include <stdint.h>

// ---------------- problem constants ----------------
#define BATCH 16
#define CH    3
#define IMG   224
#define NP    14
#define PS    16
#define D     768
#define NH    12
#define LAYERS 12
#define OUT_C 1000
#define DH    64
#define MLPD  3072
#define SEQ   197
#define NTOK  (BATCH*SEQ)    // 3152
#define NPATCH (BATCH*NP*NP) // 3136
#define EPS   1e-5f
#define ATT_SCALE 0.125f

// ---------------- scratch (device globals; allocation-free) ----------------
__device__ __align__(128) float g_out[NTOK * D];
__device__ __align__(128) float g_q  [NTOK * D];
__device__ __align__(128) float g_k  [NTOK * D];
__device__ __align__(128) float g_v  [NTOK * D];

__device__ __align__(128) __nv_bfloat16 g_xh[NTOK * D];
__device__ __align__(128) __nv_bfloat16 g_xl[NTOK * D];
__device__ __align__(128) __nv_bfloat16 g_hh[NTOK * MLPD];
__device__ __align__(128) __nv_bfloat16 g_hl[NTOK * MLPD];

__device__ __align__(128) __nv_bfloat16 g_Wmh[D * D];
__device__ __align__(128) __nv_bfloat16 g_Wml[D * D];
__device__ __align__(128) __nv_bfloat16 g_Wqkvh[LAYERS * 3 * D * D];
__device__ __align__(128) __nv_bfloat16 g_Wqkvl[LAYERS * 3 * D * D];
__device__ __align__(128) float         g_bqkv [LAYERS * 3 * D];
__device__ __align__(128) __nv_bfloat16 g_W1h[LAYERS * MLPD * D];
__device__ __align__(128) __nv_bfloat16 g_W1l[LAYERS * MLPD * D];
__device__ __align__(128) __nv_bfloat16 g_W2h[LAYERS * D * MLPD];
__device__ __align__(128) __nv_bfloat16 g_W2l[LAYERS * D * MLPD];

// ---------------- PTX helpers (base-sm_103-portable) ----------------
__device__ __forceinline__ uint32_t smem_u32(const void* p) {
    uint32_t a;
    asm("{ .reg .u64 t; cvta.to.shared.u64 t, %1; cvt.u32.u64 %0, t; }" : "=r"(a) : "l"(p));
    return a;
}
__device__ __forceinline__ void cpasync16(uint32_t s, const void* g, uint32_t sz) {
    asm volatile("cp.async.cg.shared.global [%0], [%1], 16, %2;"
                 :: "r"(s), "l"(g), "r"(sz) : "memory");
}
__device__ __forceinline__ void cp_commit() {
    asm volatile("cp.async.commit_group;" ::: "memory");
}
template<int N>
__device__ __forceinline__ void cp_wait() {
    asm volatile("cp.async.wait_group %0;" :: "n"(N) : "memory");
}
#define LDSM4(r, addr) \
    asm volatile("ldmatrix.sync.aligned.m8n8.x4.shared.b16 {%0,%1,%2,%3}, [%4];" \
        : "=r"((r)[0]), "=r"((r)[1]), "=r"((r)[2]), "=r"((r)[3]) : "r"(addr))

__device__ __forceinline__ void mma16816(float* d, const uint32_t* a, uint32_t b0, uint32_t b1) {
    asm volatile("mma.sync.aligned.m16n8k16.row.col.f32.bf16.bf16.f32 "
        "{%0,%1,%2,%3}, {%4,%5,%6,%7}, {%8,%9}, {%0,%1,%2,%3};"
        : "+f"(d[0]), "+f"(d[1]), "+f"(d[2]), "+f"(d[3])
        : "r"(a[0]), "r"(a[1]), "r"(a[2]), "r"(a[3]), "r"(b0), "r"(b1));
}

// XOR swizzle for 64B rows: bits[4:5] ^= bits[7:8]; conflict-free ldmatrix
__device__ __forceinline__ uint32_t swz(uint32_t b) { return b ^ ((b >> 3) & 0x30); }

// ---------------- misc kernels ----------------
__global__ void cvt_kernel(const float4* __restrict__ src, __nv_bfloat162* __restrict__ hi,
                           __nv_bfloat162* __restrict__ lo, int n4) {
    int i = blockIdx.x * blockDim.x + threadIdx.x;
    if (i >= n4) return;
    float4 v = src[i];
    __nv_bfloat16 h0 = __float2bfloat16(v.x), h1 = __float2bfloat16(v.y);
    __nv_bfloat16 h2 = __float2bfloat16(v.z), h3 = __float2bfloat16(v.w);
    hi[i*2+0] = __nv_bfloat162(h0, h1);
    hi[i*2+1] = __nv_bfloat162(h2, h3);
    lo[i*2+0] = __nv_bfloat162(__float2bfloat16(v.x - __bfloat162float(h0)),
                               __float2bfloat16(v.y - __bfloat162float(h1)));
    lo[i*2+1] = __nv_bfloat162(__float2bfloat16(v.z - __bfloat162float(h2)),
                               __float2bfloat16(v.w - __bfloat162float(h3)));
}

__global__ void cvt_qkv_kernel(const float4* __restrict__ src, __nv_bfloat162* __restrict__ hi,
                               __nv_bfloat162* __restrict__ lo, int which) {
    const int n4l = D * D / 4;
    int i = blockIdx.x * blockDim.x + threadIdx.x;
    if (i >= LAYERS * n4l) return;
    int l = i / n4l, r = i - l * n4l;
    size_t d4 = (size_t)l * (3 * n4l) + (size_t)which * n4l + r;
    float4 v = src[i];
    __nv_bfloat16 h0 = __float2bfloat16(v.x), h1 = __float2bfloat16(v.y);
    __nv_bfloat16 h2 = __float2bfloat16(v.z), h3 = __float2bfloat16(v.w);
    hi[d4*2+0] = __nv_bfloat162(h0, h1);
    hi[d4*2+1] = __nv_bfloat162(h2, h3);
    lo[d4*2+0] = __nv_bfloat162(__float2bfloat16(v.x - __bfloat162float(h0)),
                                __float2bfloat16(v.y - __bfloat162float(h1)));
    lo[d4*2+1] = __nv_bfloat162(__float2bfloat16(v.z - __bfloat162float(h2)),
                                __float2bfloat16(v.w - __bfloat162float(h3)));
}

__global__ void combine_bias_kernel(const float* __restrict__ bq, const float* __restrict__ bk,
                                    const float* __restrict__ bv, float* __restrict__ bqkv) {
    int i = blockIdx.x * blockDim.x + threadIdx.x;
    if (i >= LAYERS * 3 * D) return;
    int l = i / (3 * D), r = i - l * (3 * D);
    float v;
    if (r < D) v = bq[l * D + r];
    else if (r < 2 * D) v = bk[l * D + r - D];
    else v = bv[l * D + r - 2 * D];
    bqkv[i] = v;
}

__global__ void patchify_kernel(const float* __restrict__ images,
                                __nv_bfloat16* __restrict__ ph, __nv_bfloat16* __restrict__ pl) {
    int idx = blockIdx.x * blockDim.x + threadIdx.x;
    const int total = NPATCH * D;
    if (idx >= total) return;
    int m  = idx / D;
    int kk = idx - m * D;
    int b  = m / (NP * NP);
    int p  = m - b * (NP * NP);
    int py = p / NP, px = p - py * NP;
    int c  = kk >> 8;
    int r  = (kk >> 4) & 15;
    int col = kk & 15;
    int src = ((b * CH + c) * IMG + py * PS + r) * IMG + px * PS + col;
    float x = images[src];
    __nv_bfloat16 h = __float2bfloat16(x);
    ph[idx] = h;
    pl[idx] = __float2bfloat16(x - __bfloat162float(h));
}

__global__ void cls_init_kernel(const float* __restrict__ cls_tok, const float* __restrict__ pe,
                                float* __restrict__ out) {
    int idx = blockIdx.x * blockDim.x + threadIdx.x;
    if (idx >= BATCH * D) return;
    int b = idx / D, d = idx - b * D;
    out[(size_t)b * SEQ * D + d] = cls_tok[d] + pe[d];
}

__device__ __forceinline__ float warp_sum(float v) {
    #pragma unroll
    for (int o = 16; o; o >>= 1) v += __shfl_xor_sync(0xFFFFFFFFu, v, o);
    return v;
}
__device__ __forceinline__ float warp_max(float v) {
    #pragma unroll
    for (int o = 16; o; o >>= 1) v = fmaxf(v, __shfl_xor_sync(0xFFFFFFFFu, v, o));
    return v;
}

// ---------------- layernorm -> hi/lo bf16 ----------------
__global__ void ln_kernel(const float* __restrict__ in, const float* __restrict__ g,
                          const float* __restrict__ beta,
                          __nv_bfloat16* __restrict__ oh, __nv_bfloat16* __restrict__ ol) {
    int row = blockIdx.x;
    int tid = threadIdx.x;
    const float* x = in + (size_t)row * D;
    float v0 = x[tid], v1 = x[tid + 256], v2 = x[tid + 512];
    __shared__ float red[8];
    __shared__ float s_mean, s_rstd;
    int lane = tid & 31, w = tid >> 5;

    float s = warp_sum(v0 + v1 + v2);
    if (lane == 0) red[w] = s;
    __syncthreads();
    if (tid == 0) {
        float t = 0;
        #pragma unroll
        for (int i = 0; i < 8; i++) t += red[i];
        s_mean = t * (1.0f / D);
    }
    __syncthreads();
    float m = s_mean;
    float d0 = v0 - m, d1 = v1 - m, d2 = v2 - m;
    float vs = warp_sum(d0 * d0 + d1 * d1 + d2 * d2);
    if (lane == 0) red[w] = vs;
    __syncthreads();
    if (tid == 0) {
        float t = 0;
        #pragma unroll
        for (int i = 0; i < 8; i++) t += red[i];
        s_rstd = rsqrtf(t * (1.0f / D) + EPS);
    }
    __syncthreads();
    float rs = s_rstd;
    size_t base = (size_t)row * D;
    #pragma unroll
    for (int j = 0; j < 3; j++) {
        float dv = (j == 0 ? d0 : (j == 1 ? d1 : d2));
        int c = tid + j * 256;
        float v = dv * rs * g[c] + beta[c];
        __nv_bfloat16 h = __float2bfloat16(v);
        oh[base + c] = h;
        ol[base + c] = __float2bfloat16(v - __bfloat162float(h));
    }
}

// ---------------- HMMA GEMM: C = A[M,K] @ W[N,K]^T + bias ----------------
// 128x64 block tile, 8 warps (4x2), warp tile 32x32, K-chunk 32, 3-stage cp.async,
// SW64-swizzled 64B smem rows, 2 CTAs/SM. Term-major MMA issue: consecutive HMMAs
// hit distinct accumulators (reuse distance 8) to cover accumulator RAW latency.
#define GM_PATCH 0
#define GM_QKV   1
#define GM_GELU  2
#define GM_RES   3

#define KC 32
#define BM 128
#define BN 64
#define A_BYTES 8192                     // 128 rows x 64B
#define B_BYTES 4096                     // 64 rows x 64B
#define STAGE_BYTES (2*A_BYTES + 2*B_BYTES)  // 24576
#define OFF_AL A_BYTES
#define OFF_BH (2*A_BYTES)
#define OFF_BL (2*A_BYTES + B_BYTES)
#define NSTAGE 3
#define GSM_TOTAL (NSTAGE * STAGE_BYTES) // 73728 (>= 33280 epilogue)

__device__ __forceinline__ void load_stage(
    uint32_t sb,
    const __nv_bfloat16* __restrict__ Ah, const __nv_bfloat16* __restrict__ Al,
    const __nv_bfloat16* __restrict__ Bh, const __nv_bfloat16* __restrict__ Bl,
    int bm, int bn, int kc, int K, int M, int tid)
{
    #pragma unroll
    for (int i = 0; i < 2; i++) {
        int idx = tid + i * 256;
        int row = idx >> 2, c = idx & 3;
        uint32_t so = swz((uint32_t)((row << 6) + c * 16));
        int gr = bm + row;
        bool ok = gr < M;
        size_t off = (size_t)(ok ? gr : 0) * K + kc + c * 8;
        uint32_t sz = ok ? 16u : 0u;
        cpasync16(sb + so,          Ah + off, sz);
        cpasync16(sb + OFF_AL + so, Al + off, sz);
    }
    {
        int row = tid >> 2, c = tid & 3;
        uint32_t so = swz((uint32_t)((row << 6) + c * 16));
        size_t off = (size_t)(bn + row) * K + kc + c * 8;
        cpasync16(sb + OFF_BH + so, Bh + off, 16u);
        cpasync16(sb + OFF_BL + so, Bl + off, 16u);
    }
}

template<int MODE>
__global__ __launch_bounds__(256, 2)
void gemm_mma(const __nv_bfloat16* __restrict__ Ah, const __nv_bfloat16* __restrict__ Al,
              const __nv_bfloat16* __restrict__ Bh, const __nv_bfloat16* __restrict__ Bl,
              const float* __restrict__ bias, float* __restrict__ Cd,
              float* __restrict__ Ck, float* __restrict__ Cv,
              __nv_bfloat16* __restrict__ Ch, __nv_bfloat16* __restrict__ Cl,
              const float* __restrict__ pe, int M, int N, int K) {
    extern __shared__ char sm[];
    const int tid = threadIdx.x;
    const int lane = tid & 31;
    const int wid = tid >> 5;
    const int wm = wid >> 1;            // 0..3 (M)
    const int wn = wid & 1;             // 0..1 (N)
    const int bm = blockIdx.y * BM, bn = blockIdx.x * BN;
    const int NC = K / KC;
    const uint32_t sb0 = smem_u32(sm);

    float c[2][4][4];
    #pragma unroll
    for (int i = 0; i < 2; i++)
        #pragma unroll
        for (int j = 0; j < 4; j++)
            #pragma unroll
            for (int k = 0; k < 4; k++) c[i][j][k] = 0.0f;

    const uint32_t a_row = (uint32_t)(lane & 15);
    const uint32_t a_kh  = (uint32_t)(lane >> 4);
    const uint32_t b_row = (uint32_t)(((lane >> 4) << 3) + (lane & 7));
    const uint32_t b_kh  = (uint32_t)((lane >> 3) & 1);

    load_stage(sb0,               Ah, Al, Bh, Bl, bm, bn, 0,  K, M, tid);
    cp_commit();
    load_stage(sb0 + STAGE_BYTES, Ah, Al, Bh, Bl, bm, bn, KC, K, M, tid);
    cp_commit();

    for (int cc = 0; cc < NC; cc++) {
        cp_wait<1>();
        __syncthreads();
        if (cc + 2 < NC) {
            load_stage(sb0 + ((cc + 2) % NSTAGE) * STAGE_BYTES,
                       Ah, Al, Bh, Bl, bm, bn, (cc + 2) * KC, K, M, tid);
        }
        cp_commit();

        const uint32_t st = sb0 + (cc % NSTAGE) * STAGE_BYTES;

        #pragma unroll
        for (int ks = 0; ks < 2; ks++) {
            // hoist ALL fragments for this k16 step
            uint32_t ah[2][4], al[2][4], bh[2][4], bl[2][4];
            #pragma unroll
            for (int nt = 0; nt < 2; nt++) {
                uint32_t rel = (((uint32_t)(wn * 32 + nt * 16) + b_row) << 6) + ks * 32 + b_kh * 16;
                LDSM4(bh[nt], st + OFF_BH + swz(rel));
                LDSM4(bl[nt], st + OFF_BL + swz(rel));
            }
            #pragma unroll
            for (int mt = 0; mt < 2; mt++) {
                uint32_t rel = (((uint32_t)(wm * 32 + mt * 16) + a_row) << 6) + ks * 32 + a_kh * 16;
                LDSM4(ah[mt], st + swz(rel));
                LDSM4(al[mt], st + OFF_AL + swz(rel));
            }
            // term-major issue: 8 independent accumulators per term
            #pragma unroll
            for (int mt = 0; mt < 2; mt++)
                #pragma unroll
                for (int n8 = 0; n8 < 4; n8++) {
                    int nt = n8 >> 1, p = (n8 & 1) * 2;
                    mma16816(c[mt][n8], ah[mt], bh[nt][p], bh[nt][p + 1]);
                }
            #pragma unroll
            for (int mt = 0; mt < 2; mt++)
                #pragma unroll
                for (int n8 = 0; n8 < 4; n8++) {
                    int nt = n8 >> 1, p = (n8 & 1) * 2;
                    mma16816(c[mt][n8], ah[mt], bl[nt][p], bl[nt][p + 1]);
                }
            #pragma unroll
            for (int mt = 0; mt < 2; mt++)
                #pragma unroll
                for (int n8 = 0; n8 < 4; n8++) {
                    int nt = n8 >> 1, p = (n8 & 1) * 2;
                    mma16816(c[mt][n8], al[mt], bh[nt][p], bh[nt][p + 1]);
                }
        }
    }
    __syncthreads();

    // epilogue: fragments -> smem fp32 (stride 65) -> coalesced gmem
    float* smf = (float*)sm;
    #pragma unroll
    for (int mt = 0; mt < 2; mt++) {
        #pragma unroll
        for (int n8 = 0; n8 < 4; n8++) {
            int r0 = wm * 32 + mt * 16 + (lane >> 2);
            int c0 = wn * 32 + n8 * 8 + (lane & 3) * 2;
            smf[r0 * 65 + c0]           = c[mt][n8][0];
            smf[r0 * 65 + c0 + 1]       = c[mt][n8][1];
            smf[(r0 + 8) * 65 + c0]     = c[mt][n8][2];
            smf[(r0 + 8) * 65 + c0 + 1] = c[mt][n8][3];
        }
    }
    __syncthreads();

    for (int i = tid; i < BM * BN; i += 256) {
        int rr = i >> 6, ccn = i & 63;
        int m = bm + rr;
        if (m >= M) break;
        int n = bn + ccn;
        float v = smf[rr * 65 + ccn] + bias[n];
        if (MODE == GM_PATCH) {
            int b = m / (NP * NP);
            int p = m - b * (NP * NP);
            int s = p + 1;
            Cd[((size_t)b * SEQ + s) * D + n] = v + pe[(size_t)s * D + n];
        } else if (MODE == GM_QKV) {
            float* dst = (n < D) ? Cd : ((n < 2 * D) ? Ck : Cv);
            int nn = (n < D) ? n : ((n < 2 * D) ? n - D : n - 2 * D);
            dst[(size_t)m * D + nn] = v;
        } else if (MODE == GM_GELU) {
            float t = 0.5f * v * (1.0f + erff(v * 0.70710678118654752f));
            __nv_bfloat16 h = __float2bfloat16(t);
            Ch[(size_t)m * N + n] = h;
            Cl[(size_t)m * N + n] = __float2bfloat16(t - __bfloat162float(h));
        } else { // GM_RES
            Cd[(size_t)m * N + n] += v;
        }
    }
}

// ---------------- attention (fp32 SIMT, register-tiled) ----------------
#define ATT_KV_STRIDE 65
#define ATT_QB_OFF   (2 * SEQ * ATT_KV_STRIDE)
#define ATT_SC_OFF   (ATT_QB_OFF + 8 * 8 * ATT_KV_STRIDE)
#define ATT_SMEM_FLOATS (ATT_SC_OFF + 8 * 8 * 256)
#define ATT_SMEM_BYTES  (ATT_SMEM_FLOATS * 4)

__global__ __launch_bounds__(256, 1)
void attn_kernel(const float* __restrict__ q, const float* __restrict__ k,
                 const float* __restrict__ v, float* __restrict__ out) {
    extern __shared__ float smf[];
    float* ks = smf;
    float* vs = ks + SEQ * ATT_KV_STRIDE;

    int bh = blockIdx.x;
    int b = bh / NH, h = bh - b * NH;
    int tid = threadIdx.x, lane = tid & 31, w = tid >> 5;

    float* qb = smf + ATT_QB_OFF + w * (8 * ATT_KV_STRIDE);
    float* sc = smf + ATT_SC_OFF + w * (8 * 256);

    for (int i = tid; i < SEQ * 64; i += 256) {
        int t = i >> 6, e = i & 63;
        size_t src = ((size_t)(b * SEQ + t)) * D + h * 64 + e;
        ks[t * ATT_KV_STRIDE + e] = k[src];
        vs[t * ATT_KV_STRIDE + e] = v[src];
    }
    __syncthreads();

    for (int s0 = w * 8; s0 < SEQ; s0 += 64) {
        int nr = SEQ - s0; if (nr > 8) nr = 8;

        #pragma unroll
        for (int r = 0; r < 8; r++) {
            if (r < nr) {
                size_t qi = ((size_t)(b * SEQ + s0 + r)) * D + h * 64;
                qb[r * ATT_KV_STRIDE + lane]      = q[qi + lane];
                qb[r * ATT_KV_STRIDE + lane + 32] = q[qi + lane + 32];
            }
        }
        __syncwarp();

        float acc[8][8];
        #pragma unroll
        for (int r = 0; r < 8; r++)
            #pragma unroll
            for (int j = 0; j < 8; j++) acc[r][j] = 0.0f;

        for (int e = 0; e < 64; e++) {
            float kt[8];
            #pragma unroll
            for (int j = 0; j < 8; j++) {
                int t = lane + 32 * j;
                kt[j] = ks[t * ATT_KV_STRIDE + e];
            }
            #pragma unroll
            for (int r = 0; r < 8; r++) {
                float qv = qb[r * ATT_KV_STRIDE + e];
                #pragma unroll
                for (int j = 0; j < 8; j++) acc[r][j] = fmaf(qv, kt[j], acc[r][j]);
            }
        }
        #pragma unroll
        for (int r = 0; r < 8; r++) {
            if (r < nr) {
                #pragma unroll
                for (int j = 0; j < 8; j++) {
                    int t = lane + 32 * j;
                    if (t < SEQ) sc[r * 256 + t] = acc[r][j] * ATT_SCALE;
                }
            }
        }
        __syncwarp();

        float inv[8];
        #pragma unroll
        for (int r = 0; r < 8; r++) {
            if (r >= nr) { inv[r] = 0.0f; continue; }
            float mx = -1e30f;
            for (int t = lane; t < SEQ; t += 32) mx = fmaxf(mx, sc[r * 256 + t]);
            mx = warp_max(mx);
            float sum = 0.0f;
            for (int t = lane; t < SEQ; t += 32) {
                float e = expf(sc[r * 256 + t] - mx);
                sc[r * 256 + t] = e;
                sum += e;
            }
            sum = warp_sum(sum);
            inv[r] = 1.0f / sum;
        }
        __syncwarp();

        float a0[8], a1[8];
        #pragma unroll
        for (int r = 0; r < 8; r++) { a0[r] = 0.0f; a1[r] = 0.0f; }
        for (int t = 0; t < SEQ; t++) {
            float v0 = vs[t * ATT_KV_STRIDE + lane];
            float v1 = vs[t * ATT_KV_STRIDE + lane + 32];
            #pragma unroll
            for (int r = 0; r < 8; r++) {
                float pp = sc[r * 256 + t];
                a0[r] = fmaf(pp, v0, a0[r]);
                a1[r] = fmaf(pp, v1, a1[r]);
            }
        }
        #pragma unroll
        for (int r = 0; r < 8; r++) {
            if (r < nr) {
                size_t qi = ((size_t)(b * SEQ + s0 + r)) * D + h * 64;
                out[qi + lane]      += a0[r] * inv[r];
                out[qi + lane + 32] += a1[r] * inv[r];
            }
        }
        __syncwarp();
    }
}

// ---------------- classifier ----------------
__global__ __launch_bounds__(256)
void classifier_kernel(const float* __restrict__ out, const float* __restrict__ Wc,
                       const float* __restrict__ bc, float* __restrict__ y) {
    int b = blockIdx.x;
    int tid = threadIdx.x, lane = tid & 31, w = tid >> 5;
    __shared__ float pooled[D];
    __shared__ float logits[OUT_C];
    __shared__ float red[8];
    __shared__ float s_mx, s_sum;

    for (int d = tid; d < D; d += 256) pooled[d] = out[((size_t)b * SEQ) * D + d];
    __syncthreads();
    for (int c = tid; c < OUT_C; c += 256) {
        float s = bc[c];
        const float* wr = Wc + (size_t)c * D;
        #pragma unroll 4
        for (int kk = 0; kk < D; kk++) s = fmaf(pooled[kk], wr[kk], s);
        logits[c] = s;
    }
    __syncthreads();
    float mx = -1e30f;
    for (int c = tid; c < OUT_C; c += 256) mx = fmaxf(mx, logits[c]);
    mx = warp_max(mx);
    if (lane == 0) red[w] = mx;
    __syncthreads();
    if (tid == 0) {
        float t = red[0];
        #pragma unroll
        for (int i = 1; i < 8; i++) t = fmaxf(t, red[i]);
        s_mx = t;
    }
    __syncthreads();
    mx = s_mx;
    float sum = 0.0f;
    for (int c = tid; c < OUT_C; c += 256) {
        float e = expf(logits[c] - mx);
        logits[c] = e;
        sum += e;
    }
    sum = warp_sum(sum);
    if (lane == 0) red[w] = sum;
    __syncthreads();
    if (tid == 0) {
        float t = 0;
        #pragma unroll
        for (int i = 0; i < 8; i++) t += red[i];
        s_sum = t;
    }
    __syncthreads();
    float inv = 1.0f / s_sum;
    for (int c = tid; c < OUT_C; c += 256) y[(size_t)b * OUT_C + c] = logits[c] * inv;
}

// ---------------- host orchestration ----------------
static void cvt(const float* src, __nv_bfloat16* hi, __nv_bfloat16* lo, int n) {
    int n4 = n / 4;
    cvt_kernel<<<(n4 + 255) / 256, 256>>>((const float4*)src, (__nv_bfloat162*)hi,
                                          (__nv_bfloat162*)lo, n4);
}

extern "C" void kernel_launch(void* const* d_in, const int* in_sizes, int n_in,
                              void* d_out, int out_size) {
    const float* images = (const float*)d_in[0];
    const float* Wm     = (const float*)d_in[1];
    const float* bm     = (const float*)d_in[2];
    const float* cls    = (const float*)d_in[3];
    const float* pe     = (const float*)d_in[4];
    const float* g1     = (const float*)d_in[5];
    const float* beta1  = (const float*)d_in[6];
    const float* Wq     = (const float*)d_in[7];
    const float* bq     = (const float*)d_in[8];
    const float* Wk     = (const float*)d_in[9];
    const float* bk     = (const float*)d_in[10];
    const float* Wv     = (const float*)d_in[11];
    const float* bv     = (const float*)d_in[12];
    const float* g2     = (const float*)d_in[13];
    const float* beta2  = (const float*)d_in[14];
    const float* W1     = (const float*)d_in[15];
    const float* b1     = (const float*)d_in[16];
    const float* W2     = (const float*)d_in[17];
    const float* b2     = (const float*)d_in[18];
    const float* Wc     = (const float*)d_in[19];
    const float* bc     = (const float*)d_in[20];
    float* y = (float*)d_out;

    cudaFuncSetAttribute(attn_kernel, cudaFuncAttributeMaxDynamicSharedMemorySize, ATT_SMEM_BYTES);
    cudaFuncSetAttribute(gemm_mma<GM_PATCH>, cudaFuncAttributeMaxDynamicSharedMemorySize, GSM_TOTAL);
    cudaFuncSetAttribute(gemm_mma<GM_QKV>,   cudaFuncAttributeMaxDynamicSharedMemorySize, GSM_TOTAL);
    cudaFuncSetAttribute(gemm_mma<GM_GELU>,  cudaFuncAttributeMaxDynamicSharedMemorySize, GSM_TOTAL);
    cudaFuncSetAttribute(gemm_mma<GM_RES>,   cudaFuncAttributeMaxDynamicSharedMemorySize, GSM_TOTAL);

    float *p_out, *p_q, *p_k, *p_v, *p_bqkv;
    __nv_bfloat16 *p_xh, *p_xl, *p_hh, *p_hl;
    __nv_bfloat16 *wmh, *wml, *wqkvh, *wqkvl, *w1h, *w1l, *w2h, *w2l;
    cudaGetSymbolAddress((void**)&p_out, g_out);
    cudaGetSymbolAddress((void**)&p_q,   g_q);
    cudaGetSymbolAddress((void**)&p_k,   g_k);
    cudaGetSymbolAddress((void**)&p_v,   g_v);
    cudaGetSymbolAddress((void**)&p_xh,  g_xh);
    cudaGetSymbolAddress((void**)&p_xl,  g_xl);
    cudaGetSymbolAddress((void**)&p_hh,  g_hh);
    cudaGetSymbolAddress((void**)&p_hl,  g_hl);
    cudaGetSymbolAddress((void**)&wmh,   g_Wmh);
    cudaGetSymbolAddress((void**)&wml,   g_Wml);
    cudaGetSymbolAddress((void**)&wqkvh, g_Wqkvh);
    cudaGetSymbolAddress((void**)&wqkvl, g_Wqkvl);
    cudaGetSymbolAddress((void**)&p_bqkv,g_bqkv);
    cudaGetSymbolAddress((void**)&w1h,   g_W1h);
    cudaGetSymbolAddress((void**)&w1l,   g_W1l);
    cudaGetSymbolAddress((void**)&w2h,   g_W2h);
    cudaGetSymbolAddress((void**)&w2l,   g_W2l);

    // Launch order: ncu capture hits our launch index 3 -> keep patch GEMM there.
    int n4 = LAYERS * D * D / 4;
    int blocks = (n4 + 255) / 256;
    cvt(Wm, wmh, wml, D * D);                                                 // 0
    patchify_kernel<<<(NPATCH * D + 255) / 256, 256>>>(images, p_xh, p_xl);   // 1
    cvt_qkv_kernel<<<blocks, 256>>>((const float4*)Wq, (__nv_bfloat162*)wqkvh,
                                    (__nv_bfloat162*)wqkvl, 0);               // 2
    {
        dim3 grid(D / BN, (NPATCH + BM - 1) / BM);
        gemm_mma<GM_PATCH><<<grid, 256, GSM_TOTAL>>>(p_xh, p_xl, wmh, wml, bm,
                                                     p_out, nullptr, nullptr,
                                                     nullptr, nullptr, pe,
                                                     NPATCH, D, D);           // 3 <- profiled
    }
    cvt_qkv_kernel<<<blocks, 256>>>((const float4*)Wk, (__nv_bfloat162*)wqkvh,
                                    (__nv_bfloat162*)wqkvl, 1);
    cvt_qkv_kernel<<<blocks, 256>>>((const float4*)Wv, (__nv_bfloat162*)wqkvh,
                                    (__nv_bfloat162*)wqkvl, 2);
    combine_bias_kernel<<<(LAYERS * 3 * D + 255) / 256, 256>>>(bq, bk, bv, p_bqkv);
    cvt(W1, w1h, w1l, LAYERS * MLPD * D);
    cvt(W2, w2h, w2l, LAYERS * D * MLPD);
    cls_init_kernel<<<(BATCH * D + 255) / 256, 256>>>(cls, pe, p_out);

    for (int l = 0; l < LAYERS; l++) {
        const float* g1l = g1 + (size_t)l * D;
        const float* be1 = beta1 + (size_t)l * D;
        const float* g2l = g2 + (size_t)l * D;
        const float* be2 = beta2 + (size_t)l * D;
        size_t qkvoff = (size_t)l * 3 * D * D;
        size_t moff = (size_t)l * MLPD * D;
        const float* bqkvl = p_bqkv + (size_t)l * 3 * D;
        const float* b1l = b1 + (size_t)l * MLPD;
        const float* b2l = b2 + (size_t)l * D;

        ln_kernel<<<NTOK, 256>>>(p_out, g1l, be1, p_xh, p_xl);

        dim3 gqkv(3 * D / BN, (NTOK + BM - 1) / BM);
        gemm_mma<GM_QKV><<<gqkv, 256, GSM_TOTAL>>>(p_xh, p_xl, wqkvh + qkvoff, wqkvl + qkvoff,
                                                   bqkvl, p_q, p_k, p_v,
                                                   nullptr, nullptr, nullptr, NTOK, 3 * D, D);

        attn_kernel<<<BATCH * NH, 256, ATT_SMEM_BYTES>>>(p_q, p_k, p_v, p_out);

        ln_kernel<<<NTOK, 256>>>(p_out, g2l, be2, p_xh, p_xl);

        dim3 gm1(MLPD / BN, (NTOK + BM - 1) / BM);
        gemm_mma<GM_GELU><<<gm1, 256, GSM_TOTAL>>>(p_xh, p_xl, w1h + moff, w1l + moff, b1l,
                                                   nullptr, nullptr, nullptr,
                                                   p_hh, p_hl, nullptr, NTOK, MLPD, D);

        dim3 gm2(D / BN, (NTOK + BM - 1) / BM);
        gemm_mma<GM_RES><<<gm2, 256, GSM_TOTAL>>>(p_hh, p_hl, w2h + moff, w2l + moff, b2l,
                                                  p_out, nullptr, nullptr,
                                                  nullptr, nullptr, nullptr, NTOK, D, MLPD);
    }

    classifier_kernel<<<BATCH, 256>>>(p_out, Wc, bc, y);
}

// round 17
// speedup vs baseline: 1.2505x; 1.2505x over previous
#include <cuda_runtime.h>
#include <cuda_bf16.h>
#include <cuda_fp16.h>
#include <math.h>
#include <stdint.h>

// ---------------- problem constants ----------------
#define BATCH 16
#define CH    3
#define IMG   224
#define NP    14
#define PS    16
#define D     768
#define NH    12
#define LAYERS 12
#define OUT_C 1000
#define DH    64
#define MLPD  3072
#define SEQ   197
#define NTOK  (BATCH*SEQ)    // 3152
#define NPATCH (BATCH*NP*NP) // 3136
#define EPS   1e-5f
#define ATT_SCALE 0.125f

// ---------------- scratch (device globals; allocation-free) ----------------
__device__ __align__(128) float g_out[NTOK * D];
__device__ __align__(128) float g_q  [NTOK * D];
__device__ __align__(128) float g_k  [NTOK * D];
__device__ __align__(128) float g_v  [NTOK * D];

// single-fp16 activations
__device__ __align__(128) __half g_x[NTOK * D];
__device__ __align__(128) __half g_h[NTOK * MLPD];

// fp16 hi/lo split weights
__device__ __align__(128) __half g_Wmh[D * D];
__device__ __align__(128) __half g_Wml[D * D];
__device__ __align__(128) __half g_Wqkvh[LAYERS * 3 * D * D];
__device__ __align__(128) __half g_Wqkvl[LAYERS * 3 * D * D];
__device__ __align__(128) float  g_bqkv [LAYERS * 3 * D];
__device__ __align__(128) __half g_W1h[LAYERS * MLPD * D];
__device__ __align__(128) __half g_W1l[LAYERS * MLPD * D];
__device__ __align__(128) __half g_W2h[LAYERS * D * MLPD];
__device__ __align__(128) __half g_W2l[LAYERS * D * MLPD];

// ---------------- PTX helpers (base-sm_103-portable) ----------------
__device__ __forceinline__ uint32_t smem_u32(const void* p) {
    uint32_t a;
    asm("{ .reg .u64 t; cvta.to.shared.u64 t, %1; cvt.u32.u64 %0, t; }" : "=r"(a) : "l"(p));
    return a;
}
__device__ __forceinline__ void cpasync16(uint32_t s, const void* g, uint32_t sz) {
    asm volatile("cp.async.cg.shared.global [%0], [%1], 16, %2;"
                 :: "r"(s), "l"(g), "r"(sz) : "memory");
}
__device__ __forceinline__ void cp_commit() {
    asm volatile("cp.async.commit_group;" ::: "memory");
}
template<int N>
__device__ __forceinline__ void cp_wait() {
    asm volatile("cp.async.wait_group %0;" :: "n"(N) : "memory");
}
#define LDSM4(r, addr) \
    asm volatile("ldmatrix.sync.aligned.m8n8.x4.shared.b16 {%0,%1,%2,%3}, [%4];" \
        : "=r"((r)[0]), "=r"((r)[1]), "=r"((r)[2]), "=r"((r)[3]) : "r"(addr))

// fp16 inputs, fp32 accumulate
__device__ __forceinline__ void mma16816h(float* d, const uint32_t* a, uint32_t b0, uint32_t b1) {
    asm volatile("mma.sync.aligned.m16n8k16.row.col.f32.f16.f16.f32 "
        "{%0,%1,%2,%3}, {%4,%5,%6,%7}, {%8,%9}, {%0,%1,%2,%3};"
        : "+f"(d[0]), "+f"(d[1]), "+f"(d[2]), "+f"(d[3])
        : "r"(a[0]), "r"(a[1]), "r"(a[2]), "r"(a[3]), "r"(b0), "r"(b1));
}

// XOR swizzle for 64B rows: bits[4:5] ^= bits[7:8]; conflict-free ldmatrix
__device__ __forceinline__ uint32_t swz(uint32_t b) { return b ^ ((b >> 3) & 0x30); }

// ---------------- misc kernels ----------------
// weights: fp32 -> fp16 hi/lo
__global__ void cvt_kernel(const float4* __restrict__ src, __half2* __restrict__ hi,
                           __half2* __restrict__ lo, int n4) {
    int i = blockIdx.x * blockDim.x + threadIdx.x;
    if (i >= n4) return;
    float4 v = src[i];
    __half h0 = __float2half_rn(v.x), h1 = __float2half_rn(v.y);
    __half h2 = __float2half_rn(v.z), h3 = __float2half_rn(v.w);
    hi[i*2+0] = __halves2half2(h0, h1);
    hi[i*2+1] = __halves2half2(h2, h3);
    lo[i*2+0] = __halves2half2(__float2half_rn(v.x - __half2float(h0)),
                               __float2half_rn(v.y - __half2float(h1)));
    lo[i*2+1] = __halves2half2(__float2half_rn(v.z - __half2float(h2)),
                               __float2half_rn(v.w - __half2float(h3)));
}

// converts one of Wq/Wk/Wv ([L][D][D]) into combined [L][3D][D] at row-offset which*D
__global__ void cvt_qkv_kernel(const float4* __restrict__ src, __half2* __restrict__ hi,
                               __half2* __restrict__ lo, int which) {
    const int n4l = D * D / 4;
    int i = blockIdx.x * blockDim.x + threadIdx.x;
    if (i >= LAYERS * n4l) return;
    int l = i / n4l, r = i - l * n4l;
    size_t d4 = (size_t)l * (3 * n4l) + (size_t)which * n4l + r;
    float4 v = src[i];
    __half h0 = __float2half_rn(v.x), h1 = __float2half_rn(v.y);
    __half h2 = __float2half_rn(v.z), h3 = __float2half_rn(v.w);
    hi[d4*2+0] = __halves2half2(h0, h1);
    hi[d4*2+1] = __halves2half2(h2, h3);
    lo[d4*2+0] = __halves2half2(__float2half_rn(v.x - __half2float(h0)),
                                __float2half_rn(v.y - __half2float(h1)));
    lo[d4*2+1] = __halves2half2(__float2half_rn(v.z - __half2float(h2)),
                                __float2half_rn(v.w - __half2float(h3)));
}

__global__ void combine_bias_kernel(const float* __restrict__ bq, const float* __restrict__ bk,
                                    const float* __restrict__ bv, float* __restrict__ bqkv) {
    int i = blockIdx.x * blockDim.x + threadIdx.x;
    if (i >= LAYERS * 3 * D) return;
    int l = i / (3 * D), r = i - l * (3 * D);
    float v;
    if (r < D) v = bq[l * D + r];
    else if (r < 2 * D) v = bk[l * D + r - D];
    else v = bv[l * D + r - 2 * D];
    bqkv[i] = v;
}

__global__ void patchify_kernel(const float* __restrict__ images, __half* __restrict__ ph) {
    int idx = blockIdx.x * blockDim.x + threadIdx.x;
    const int total = NPATCH * D;
    if (idx >= total) return;
    int m  = idx / D;
    int kk = idx - m * D;
    int b  = m / (NP * NP);
    int p  = m - b * (NP * NP);
    int py = p / NP, px = p - py * NP;
    int c  = kk >> 8;
    int r  = (kk >> 4) & 15;
    int col = kk & 15;
    int src = ((b * CH + c) * IMG + py * PS + r) * IMG + px * PS + col;
    ph[idx] = __float2half_rn(images[src]);
}

__global__ void cls_init_kernel(const float* __restrict__ cls_tok, const float* __restrict__ pe,
                                float* __restrict__ out) {
    int idx = blockIdx.x * blockDim.x + threadIdx.x;
    if (idx >= BATCH * D) return;
    int b = idx / D, d = idx - b * D;
    out[(size_t)b * SEQ * D + d] = cls_tok[d] + pe[d];
}

__device__ __forceinline__ float warp_sum(float v) {
    #pragma unroll
    for (int o = 16; o; o >>= 1) v += __shfl_xor_sync(0xFFFFFFFFu, v, o);
    return v;
}
__device__ __forceinline__ float warp_max(float v) {
    #pragma unroll
    for (int o = 16; o; o >>= 1) v = fmaxf(v, __shfl_xor_sync(0xFFFFFFFFu, v, o));
    return v;
}

// ---------------- layernorm -> single fp16 ----------------
__global__ void ln_kernel(const float* __restrict__ in, const float* __restrict__ g,
                          const float* __restrict__ beta, __half* __restrict__ oh) {
    int row = blockIdx.x;
    int tid = threadIdx.x;
    const float* x = in + (size_t)row * D;
    float v0 = x[tid], v1 = x[tid + 256], v2 = x[tid + 512];
    __shared__ float red[8];
    __shared__ float s_mean, s_rstd;
    int lane = tid & 31, w = tid >> 5;

    float s = warp_sum(v0 + v1 + v2);
    if (lane == 0) red[w] = s;
    __syncthreads();
    if (tid == 0) {
        float t = 0;
        #pragma unroll
        for (int i = 0; i < 8; i++) t += red[i];
        s_mean = t * (1.0f / D);
    }
    __syncthreads();
    float m = s_mean;
    float d0 = v0 - m, d1 = v1 - m, d2 = v2 - m;
    float vs = warp_sum(d0 * d0 + d1 * d1 + d2 * d2);
    if (lane == 0) red[w] = vs;
    __syncthreads();
    if (tid == 0) {
        float t = 0;
        #pragma unroll
        for (int i = 0; i < 8; i++) t += red[i];
        s_rstd = rsqrtf(t * (1.0f / D) + EPS);
    }
    __syncthreads();
    float rs = s_rstd;
    size_t base = (size_t)row * D;
    #pragma unroll
    for (int j = 0; j < 3; j++) {
        float dv = (j == 0 ? d0 : (j == 1 ? d1 : d2));
        int c = tid + j * 256;
        oh[base + c] = __float2half_rn(dv * rs * g[c] + beta[c]);
    }
}

// ---------------- HMMA GEMM: C = A[M,K] @ W[N,K]^T + bias ----------------
// fp16 2-term: C = A*Wh + A*Wl (A single-rounded fp16, W split hi/lo).
// 128x64 block tile, 8 warps (4x2), warp tile 32x32, K-chunk 32, 4-stage cp.async,
// SW64-swizzled 64B smem rows, 2 CTAs/SM.
#define GM_PATCH 0
#define GM_QKV   1
#define GM_GELU  2
#define GM_RES   3

#define KC 32
#define BM 128
#define BN 64
#define A_BYTES 8192                     // 128 rows x 64B
#define B_BYTES 4096                     // 64 rows x 64B
#define STAGE_BYTES (A_BYTES + 2*B_BYTES)   // 16384
#define OFF_BH A_BYTES
#define OFF_BL (A_BYTES + B_BYTES)
#define NSTAGE 4
#define GSM_TOTAL (NSTAGE * STAGE_BYTES) // 65536 (>= 33280 epilogue)

__device__ __forceinline__ void load_stage(
    uint32_t sb,
    const __half* __restrict__ A,
    const __half* __restrict__ Bh, const __half* __restrict__ Bl,
    int bm, int bn, int kc, int K, int M, int tid)
{
    // A: 128 rows x 4 chunks = 512; 2 per thread
    #pragma unroll
    for (int i = 0; i < 2; i++) {
        int idx = tid + i * 256;
        int row = idx >> 2, c = idx & 3;
        uint32_t so = swz((uint32_t)((row << 6) + c * 16));
        int gr = bm + row;
        bool ok = gr < M;
        size_t off = (size_t)(ok ? gr : 0) * K + kc + c * 8;
        cpasync16(sb + so, A + off, ok ? 16u : 0u);
    }
    // B: 64 rows x 4 chunks = 256; 1 per thread each tensor
    {
        int row = tid >> 2, c = tid & 3;
        uint32_t so = swz((uint32_t)((row << 6) + c * 16));
        size_t off = (size_t)(bn + row) * K + kc + c * 8;
        cpasync16(sb + OFF_BH + so, Bh + off, 16u);
        cpasync16(sb + OFF_BL + so, Bl + off, 16u);
    }
}

template<int MODE>
__global__ __launch_bounds__(256, 2)
void gemm_mma(const __half* __restrict__ A,
              const __half* __restrict__ Bh, const __half* __restrict__ Bl,
              const float* __restrict__ bias, float* __restrict__ Cd,
              float* __restrict__ Ck, float* __restrict__ Cv,
              __half* __restrict__ Ch,
              const float* __restrict__ pe, int M, int N, int K) {
    extern __shared__ char sm[];
    const int tid = threadIdx.x;
    const int lane = tid & 31;
    const int wid = tid >> 5;
    const int wm = wid >> 1;            // 0..3 (M)
    const int wn = wid & 1;             // 0..1 (N)
    const int bm = blockIdx.y * BM, bn = blockIdx.x * BN;
    const int NC = K / KC;
    const uint32_t sb0 = smem_u32(sm);

    float c[2][4][4];
    #pragma unroll
    for (int i = 0; i < 2; i++)
        #pragma unroll
        for (int j = 0; j < 4; j++)
            #pragma unroll
            for (int k = 0; k < 4; k++) c[i][j][k] = 0.0f;

    const uint32_t a_row = (uint32_t)(lane & 15);
    const uint32_t a_kh  = (uint32_t)(lane >> 4);
    const uint32_t b_row = (uint32_t)(((lane >> 4) << 3) + (lane & 7));
    const uint32_t b_kh  = (uint32_t)((lane >> 3) & 1);

    // prologue: fill stages 0..2
    load_stage(sb0,                   A, Bh, Bl, bm, bn, 0,      K, M, tid);
    cp_commit();
    load_stage(sb0 + STAGE_BYTES,     A, Bh, Bl, bm, bn, KC,     K, M, tid);
    cp_commit();
    load_stage(sb0 + 2 * STAGE_BYTES, A, Bh, Bl, bm, bn, 2 * KC, K, M, tid);
    cp_commit();

    for (int cc = 0; cc < NC; cc++) {
        cp_wait<2>();
        __syncthreads();
        if (cc + 3 < NC) {
            load_stage(sb0 + ((cc + 3) % NSTAGE) * STAGE_BYTES,
                       A, Bh, Bl, bm, bn, (cc + 3) * KC, K, M, tid);
        }
        cp_commit();

        const uint32_t st = sb0 + (cc % NSTAGE) * STAGE_BYTES;

        #pragma unroll
        for (int ks = 0; ks < 2; ks++) {
            uint32_t ah[2][4], bh[2][4], bl[2][4];
            #pragma unroll
            for (int nt = 0; nt < 2; nt++) {
                uint32_t rel = (((uint32_t)(wn * 32 + nt * 16) + b_row) << 6) + ks * 32 + b_kh * 16;
                LDSM4(bh[nt], st + OFF_BH + swz(rel));
                LDSM4(bl[nt], st + OFF_BL + swz(rel));
            }
            #pragma unroll
            for (int mt = 0; mt < 2; mt++) {
                uint32_t rel = (((uint32_t)(wm * 32 + mt * 16) + a_row) << 6) + ks * 32 + a_kh * 16;
                LDSM4(ah[mt], st + swz(rel));
            }
            #pragma unroll
            for (int mt = 0; mt < 2; mt++)
                #pragma unroll
                for (int n8 = 0; n8 < 4; n8++) {
                    int nt = n8 >> 1, p = (n8 & 1) * 2;
                    mma16816h(c[mt][n8], ah[mt], bh[nt][p], bh[nt][p + 1]);
                }
            #pragma unroll
            for (int mt = 0; mt < 2; mt++)
                #pragma unroll
                for (int n8 = 0; n8 < 4; n8++) {
                    int nt = n8 >> 1, p = (n8 & 1) * 2;
                    mma16816h(c[mt][n8], ah[mt], bl[nt][p], bl[nt][p + 1]);
                }
        }
    }
    __syncthreads();

    // epilogue: fragments -> smem fp32 (stride 65) -> coalesced gmem
    float* smf = (float*)sm;
    #pragma unroll
    for (int mt = 0; mt < 2; mt++) {
        #pragma unroll
        for (int n8 = 0; n8 < 4; n8++) {
            int r0 = wm * 32 + mt * 16 + (lane >> 2);
            int c0 = wn * 32 + n8 * 8 + (lane & 3) * 2;
            smf[r0 * 65 + c0]           = c[mt][n8][0];
            smf[r0 * 65 + c0 + 1]       = c[mt][n8][1];
            smf[(r0 + 8) * 65 + c0]     = c[mt][n8][2];
            smf[(r0 + 8) * 65 + c0 + 1] = c[mt][n8][3];
        }
    }
    __syncthreads();

    for (int i = tid; i < BM * BN; i += 256) {
        int rr = i >> 6, ccn = i & 63;
        int m = bm + rr;
        if (m >= M) break;
        int n = bn + ccn;
        float v = smf[rr * 65 + ccn] + bias[n];
        if (MODE == GM_PATCH) {
            int b = m / (NP * NP);
            int p = m - b * (NP * NP);
            int s = p + 1;
            Cd[((size_t)b * SEQ + s) * D + n] = v + pe[(size_t)s * D + n];
        } else if (MODE == GM_QKV) {
            float* dst = (n < D) ? Cd : ((n < 2 * D) ? Ck : Cv);
            int nn = (n < D) ? n : ((n < 2 * D) ? n - D : n - 2 * D);
            dst[(size_t)m * D + nn] = v;
        } else if (MODE == GM_GELU) {
            float t = 0.5f * v * (1.0f + erff(v * 0.70710678118654752f));
            Ch[(size_t)m * N + n] = __float2half_rn(t);
        } else { // GM_RES
            Cd[(size_t)m * N + n] += v;
        }
    }
}

// ---------------- attention (fp32 SIMT, register-tiled) ----------------
#define ATT_KV_STRIDE 65
#define ATT_QB_OFF   (2 * SEQ * ATT_KV_STRIDE)
#define ATT_SC_OFF   (ATT_QB_OFF + 8 * 8 * ATT_KV_STRIDE)
#define ATT_SMEM_FLOATS (ATT_SC_OFF + 8 * 8 * 256)
#define ATT_SMEM_BYTES  (ATT_SMEM_FLOATS * 4)

__global__ __launch_bounds__(256, 1)
void attn_kernel(const float* __restrict__ q, const float* __restrict__ k,
                 const float* __restrict__ v, float* __restrict__ out) {
    extern __shared__ float smf[];
    float* ks = smf;
    float* vs = ks + SEQ * ATT_KV_STRIDE;

    int bh = blockIdx.x;
    int b = bh / NH, h = bh - b * NH;
    int tid = threadIdx.x, lane = tid & 31, w = tid >> 5;

    float* qb = smf + ATT_QB_OFF + w * (8 * ATT_KV_STRIDE);
    float* sc = smf + ATT_SC_OFF + w * (8 * 256);

    for (int i = tid; i < SEQ * 64; i += 256) {
        int t = i >> 6, e = i & 63;
        size_t src = ((size_t)(b * SEQ + t)) * D + h * 64 + e;
        ks[t * ATT_KV_STRIDE + e] = k[src];
        vs[t * ATT_KV_STRIDE + e] = v[src];
    }
    __syncthreads();

    for (int s0 = w * 8; s0 < SEQ; s0 += 64) {
        int nr = SEQ - s0; if (nr > 8) nr = 8;

        #pragma unroll
        for (int r = 0; r < 8; r++) {
            if (r < nr) {
                size_t qi = ((size_t)(b * SEQ + s0 + r)) * D + h * 64;
                qb[r * ATT_KV_STRIDE + lane]      = q[qi + lane];
                qb[r * ATT_KV_STRIDE + lane + 32] = q[qi + lane + 32];
            }
        }
        __syncwarp();

        float acc[8][8];
        #pragma unroll
        for (int r = 0; r < 8; r++)
            #pragma unroll
            for (int j = 0; j < 8; j++) acc[r][j] = 0.0f;

        for (int e = 0; e < 64; e++) {
            float kt[8];
            #pragma unroll
            for (int j = 0; j < 8; j++) {
                int t = lane + 32 * j;
                kt[j] = ks[t * ATT_KV_STRIDE + e];
            }
            #pragma unroll
            for (int r = 0; r < 8; r++) {
                float qv = qb[r * ATT_KV_STRIDE + e];
                #pragma unroll
                for (int j = 0; j < 8; j++) acc[r][j] = fmaf(qv, kt[j], acc[r][j]);
            }
        }
        #pragma unroll
        for (int r = 0; r < 8; r++) {
            if (r < nr) {
                #pragma unroll
                for (int j = 0; j < 8; j++) {
                    int t = lane + 32 * j;
                    if (t < SEQ) sc[r * 256 + t] = acc[r][j] * ATT_SCALE;
                }
            }
        }
        __syncwarp();

        float inv[8];
        #pragma unroll
        for (int r = 0; r < 8; r++) {
            if (r >= nr) { inv[r] = 0.0f; continue; }
            float mx = -1e30f;
            for (int t = lane; t < SEQ; t += 32) mx = fmaxf(mx, sc[r * 256 + t]);
            mx = warp_max(mx);
            float sum = 0.0f;
            for (int t = lane; t < SEQ; t += 32) {
                float e = expf(sc[r * 256 + t] - mx);
                sc[r * 256 + t] = e;
                sum += e;
            }
            sum = warp_sum(sum);
            inv[r] = 1.0f / sum;
        }
        __syncwarp();

        float a0[8], a1[8];
        #pragma unroll
        for (int r = 0; r < 8; r++) { a0[r] = 0.0f; a1[r] = 0.0f; }
        for (int t = 0; t < SEQ; t++) {
            float v0 = vs[t * ATT_KV_STRIDE + lane];
            float v1 = vs[t * ATT_KV_STRIDE + lane + 32];
            #pragma unroll
            for (int r = 0; r < 8; r++) {
                float pp = sc[r * 256 + t];
                a0[r] = fmaf(pp, v0, a0[r]);
                a1[r] = fmaf(pp, v1, a1[r]);
            }
        }
        #pragma unroll
        for (int r = 0; r < 8; r++) {
            if (r < nr) {
                size_t qi = ((size_t)(b * SEQ + s0 + r)) * D + h * 64;
                out[qi + lane]      += a0[r] * inv[r];
                out[qi + lane + 32] += a1[r] * inv[r];
            }
        }
        __syncwarp();
    }
}

// ---------------- classifier ----------------
__global__ __launch_bounds__(256)
void classifier_kernel(const float* __restrict__ out, const float* __restrict__ Wc,
                       const float* __restrict__ bc, float* __restrict__ y) {
    int b = blockIdx.x;
    int tid = threadIdx.x, lane = tid & 31, w = tid >> 5;
    __shared__ float pooled[D];
    __shared__ float logits[OUT_C];
    __shared__ float red[8];
    __shared__ float s_mx, s_sum;

    for (int d = tid; d < D; d += 256) pooled[d] = out[((size_t)b * SEQ) * D + d];
    __syncthreads();
    for (int c = tid; c < OUT_C; c += 256) {
        float s = bc[c];
        const float* wr = Wc + (size_t)c * D;
        #pragma unroll 4
        for (int kk = 0; kk < D; kk++) s = fmaf(pooled[kk], wr[kk], s);
        logits[c] = s;
    }
    __syncthreads();
    float mx = -1e30f;
    for (int c = tid; c < OUT_C; c += 256) mx = fmaxf(mx, logits[c]);
    mx = warp_max(mx);
    if (lane == 0) red[w] = mx;
    __syncthreads();
    if (tid == 0) {
        float t = red[0];
        #pragma unroll
        for (int i = 1; i < 8; i++) t = fmaxf(t, red[i]);
        s_mx = t;
    }
    __syncthreads();
    mx = s_mx;
    float sum = 0.0f;
    for (int c = tid; c < OUT_C; c += 256) {
        float e = expf(logits[c] - mx);
        logits[c] = e;
        sum += e;
    }
    sum = warp_sum(sum);
    if (lane == 0) red[w] = sum;
    __syncthreads();
    if (tid == 0) {
        float t = 0;
        #pragma unroll
        for (int i = 0; i < 8; i++) t += red[i];
        s_sum = t;
    }
    __syncthreads();
    float inv = 1.0f / s_sum;
    for (int c = tid; c < OUT_C; c += 256) y[(size_t)b * OUT_C + c] = logits[c] * inv;
}

// ---------------- host orchestration ----------------
static void cvt(const float* src, __half* hi, __half* lo, int n) {
    int n4 = n / 4;
    cvt_kernel<<<(n4 + 255) / 256, 256>>>((const float4*)src, (__half2*)hi, (__half2*)lo, n4);
}

extern "C" void kernel_launch(void* const* d_in, const int* in_sizes, int n_in,
                              void* d_out, int out_size) {
    const float* images = (const float*)d_in[0];
    const float* Wm     = (const float*)d_in[1];
    const float* bm     = (const float*)d_in[2];
    const float* cls    = (const float*)d_in[3];
    const float* pe     = (const float*)d_in[4];
    const float* g1     = (const float*)d_in[5];
    const float* beta1  = (const float*)d_in[6];
    const float* Wq     = (const float*)d_in[7];
    const float* bq     = (const float*)d_in[8];
    const float* Wk     = (const float*)d_in[9];
    const float* bk     = (const float*)d_in[10];
    const float* Wv     = (const float*)d_in[11];
    const float* bv     = (const float*)d_in[12];
    const float* g2     = (const float*)d_in[13];
    const float* beta2  = (const float*)d_in[14];
    const float* W1     = (const float*)d_in[15];
    const float* b1     = (const float*)d_in[16];
    const float* W2     = (const float*)d_in[17];
    const float* b2     = (const float*)d_in[18];
    const float* Wc     = (const float*)d_in[19];
    const float* bc     = (const float*)d_in[20];
    float* y = (float*)d_out;

    cudaFuncSetAttribute(attn_kernel, cudaFuncAttributeMaxDynamicSharedMemorySize, ATT_SMEM_BYTES);
    cudaFuncSetAttribute(gemm_mma<GM_PATCH>, cudaFuncAttributeMaxDynamicSharedMemorySize, GSM_TOTAL);
    cudaFuncSetAttribute(gemm_mma<GM_QKV>,   cudaFuncAttributeMaxDynamicSharedMemorySize, GSM_TOTAL);
    cudaFuncSetAttribute(gemm_mma<GM_GELU>,  cudaFuncAttributeMaxDynamicSharedMemorySize, GSM_TOTAL);
    cudaFuncSetAttribute(gemm_mma<GM_RES>,   cudaFuncAttributeMaxDynamicSharedMemorySize, GSM_TOTAL);

    float *p_out, *p_q, *p_k, *p_v, *p_bqkv;
    __half *p_x, *p_h;
    __half *wmh, *wml, *wqkvh, *wqkvl, *w1h, *w1l, *w2h, *w2l;
    cudaGetSymbolAddress((void**)&p_out, g_out);
    cudaGetSymbolAddress((void**)&p_q,   g_q);
    cudaGetSymbolAddress((void**)&p_k,   g_k);
    cudaGetSymbolAddress((void**)&p_v,   g_v);
    cudaGetSymbolAddress((void**)&p_x,   g_x);
    cudaGetSymbolAddress((void**)&p_h,   g_h);
    cudaGetSymbolAddress((void**)&wmh,   g_Wmh);
    cudaGetSymbolAddress((void**)&wml,   g_Wml);
    cudaGetSymbolAddress((void**)&wqkvh, g_Wqkvh);
    cudaGetSymbolAddress((void**)&wqkvl, g_Wqkvl);
    cudaGetSymbolAddress((void**)&p_bqkv,g_bqkv);
    cudaGetSymbolAddress((void**)&w1h,   g_W1h);
    cudaGetSymbolAddress((void**)&w1l,   g_W1l);
    cudaGetSymbolAddress((void**)&w2h,   g_W2h);
    cudaGetSymbolAddress((void**)&w2l,   g_W2l);

    // Launch order: ncu capture hits our launch index 3 -> keep patch GEMM there.
    int n4 = LAYERS * D * D / 4;
    int blocks = (n4 + 255) / 256;
    cvt(Wm, wmh, wml, D * D);                                                 // 0
    patchify_kernel<<<(NPATCH * D + 255) / 256, 256>>>(images, p_x);          // 1
    cvt_qkv_kernel<<<blocks, 256>>>((const float4*)Wq, (__half2*)wqkvh,
                                    (__half2*)wqkvl, 0);                      // 2
    {
        dim3 grid(D / BN, (NPATCH + BM - 1) / BM);
        gemm_mma<GM_PATCH><<<grid, 256, GSM_TOTAL>>>(p_x, wmh, wml, bm,
                                                     p_out, nullptr, nullptr,
                                                     nullptr, pe,
                                                     NPATCH, D, D);           // 3 <- profiled
    }
    cvt_qkv_kernel<<<blocks, 256>>>((const float4*)Wk, (__half2*)wqkvh,
                                    (__half2*)wqkvl, 1);
    cvt_qkv_kernel<<<blocks, 256>>>((const float4*)Wv, (__half2*)wqkvh,
                                    (__half2*)wqkvl, 2);
    combine_bias_kernel<<<(LAYERS * 3 * D + 255) / 256, 256>>>(bq, bk, bv, p_bqkv);
    cvt(W1, w1h, w1l, LAYERS * MLPD * D);
    cvt(W2, w2h, w2l, LAYERS * D * MLPD);
    cls_init_kernel<<<(BATCH * D + 255) / 256, 256>>>(cls, pe, p_out);

    for (int l = 0; l < LAYERS; l++) {
        const float* g1l = g1 + (size_t)l * D;
        const float* be1 = beta1 + (size_t)l * D;
        const float* g2l = g2 + (size_t)l * D;
        const float* be2 = beta2 + (size_t)l * D;
        size_t qkvoff = (size_t)l * 3 * D * D;
        size_t moff = (size_t)l * MLPD * D;
        const float* bqkvl = p_bqkv + (size_t)l * 3 * D;
        const float* b1l = b1 + (size_t)l * MLPD;
        const float* b2l = b2 + (size_t)l * D;

        ln_kernel<<<NTOK, 256>>>(p_out, g1l, be1, p_x);

        dim3 gqkv(3 * D / BN, (NTOK + BM - 1) / BM);
        gemm_mma<GM_QKV><<<gqkv, 256, GSM_TOTAL>>>(p_x, wqkvh + qkvoff, wqkvl + qkvoff,
                                                   bqkvl, p_q, p_k, p_v,
                                                   nullptr, nullptr, NTOK, 3 * D, D);

        attn_kernel<<<BATCH * NH, 256, ATT_SMEM_BYTES>>>(p_q, p_k, p_v, p_out);

        ln_kernel<<<NTOK, 256>>>(p_out, g2l, be2, p_x);

        dim3 gm1(MLPD / BN, (NTOK + BM - 1) / BM);
        gemm_mma<GM_GELU><<<gm1, 256, GSM_TOTAL>>>(p_x, w1h + moff, w1l + moff, b1l,
                                                   nullptr, nullptr, nullptr,
                                                   p_h, nullptr, NTOK, MLPD, D);

        dim3 gm2(D / BN, (NTOK + BM - 1) / BM);
        gemm_mma<GM_RES><<<gm2, 256, GSM_TOTAL>>>(p_h, w2h + moff, w2l + moff, b2l,
                                                  p_out, nullptr, nullptr,
                                                  nullptr, nullptr, NTOK, D, MLPD);
    }

    classifier_kernel<<<BATCH, 256>>>(p_out, Wc, bc, y);
}